// round 4
// baseline (speedup 1.0000x reference)
#include <cuda_runtime.h>
#include <cstdint>
#include <math.h>

#define DIMK 128
#define HID 256
#define TM 128
#define NTHREADS 256
#define SSTRIDE 132
#define ASTRIDE 256

#define SA_OFF (TM * SSTRIDE)              /* 16896 floats */
#define SW_OFF (SA_OFF + TM * ASTRIDE)     /* 49664 floats */
#define SW_TILE 4096
#define SMEM_FLOATS (SW_OFF + 2 * SW_TILE) /* 57856 floats */
#define SMEM_BYTES (SMEM_FLOATS * 4)       /* 231424 bytes */

// ---------------- packed f32x2 helpers (Blackwell FFMA2) ----------------
__device__ __forceinline__ unsigned long long fma2(unsigned long long a,
                                                   unsigned long long b,
                                                   unsigned long long c) {
    unsigned long long d;
    asm("fma.rn.f32x2 %0, %1, %2, %3;" : "=l"(d) : "l"(a), "l"(b), "l"(c));
    return d;
}
__device__ __forceinline__ unsigned long long pack_dup(float a) {
    unsigned long long d;
    asm("mov.b64 %0, {%1, %1};" : "=l"(d) : "f"(a));
    return d;
}
__device__ __forceinline__ float2 unpack2(unsigned long long v) {
    float lo, hi;
    asm("mov.b64 {%0, %1}, %2;" : "=f"(lo), "=f"(hi) : "l"(v));
    return make_float2(lo, hi);
}

// ---------------- cp.async helpers ----------------
__device__ __forceinline__ void cp_async16(unsigned saddr, const void* g) {
    asm volatile("cp.async.ca.shared.global [%0], [%1], 16;" ::"r"(saddr), "l"(g));
}
__device__ __forceinline__ void cp_commit() {
    asm volatile("cp.async.commit_group;" ::: "memory");
}
__device__ __forceinline__ void cp_wait0() {
    asm volatile("cp.async.wait_group 0;" ::: "memory");
}

__device__ __forceinline__ float gelu_f(float x) {
    return 0.5f * x * (1.0f + erff(x * 0.7071067811865476f));
}

// ---------------- register-blocked GEMM segment ----------------
// C[128 x N] += A[128 x 128] * B[128 x N]
// A element (row, k) at Abase[row*astride + k] (SMEM).
// B is global, row-major (128 x N), streamed via double-buffered SMEM tiles.
// acc: per-thread 8 rows x NP f32x2 column-pairs (cols = tc * 2*NP .. +2*NP-1).
template <int N, int KT, int NP>
__device__ __forceinline__ void gemm_seg(const float* __restrict__ Abase, int astride,
                                         const float* __restrict__ Bg,
                                         float* sW, unsigned long long* acc,
                                         int tr, int tc) {
    const int tid = threadIdx.x;
    constexpr int NTILE = KT * N;      // 4096 floats = 16 KB
    constexpr int NTILES = DIMK / KT;  // 8 or 4 (always even)

    // prefetch tile 0 into buffer 0 (prev gemm's last compute buffer is buf 1)
    {
        unsigned s0 = (unsigned)__cvta_generic_to_shared(sW);
        const float4* g = (const float4*)Bg;
#pragma unroll
        for (int v = 0; v < 4; v++) {
            int fidx = tid + v * NTHREADS;
            cp_async16(s0 + fidx * 16, g + fidx);
        }
        cp_commit();
    }
    cp_wait0();
    __syncthreads();

    const float* Ab = Abase + tr * 8 * astride;
    for (int t = 0; t < NTILES; t++) {
        if (t + 1 < NTILES) {
            unsigned s1 = (unsigned)__cvta_generic_to_shared(sW + ((t + 1) & 1) * NTILE);
            const float4* g = (const float4*)(Bg + (t + 1) * NTILE);
#pragma unroll
            for (int v = 0; v < 4; v++) {
                int fidx = tid + v * NTHREADS;
                cp_async16(s1 + fidx * 16, g + fidx);
            }
            cp_commit();
        }
        const float* sB = sW + (t & 1) * NTILE;
#pragma unroll 8
        for (int k = 0; k < KT; k++) {
            const int kg = t * KT + k;
            unsigned long long a2[8];
#pragma unroll
            for (int r = 0; r < 8; r++) a2[r] = pack_dup(Ab[r * astride + kg]);
            const unsigned long long* bp =
                (const unsigned long long*)(sB + k * N + tc * (2 * NP));
            unsigned long long bv[NP];
#pragma unroll
            for (int p = 0; p < NP; p++) bv[p] = bp[p];
#pragma unroll
            for (int r = 0; r < 8; r++) {
#pragma unroll
                for (int p = 0; p < NP; p++)
                    acc[r * NP + p] = fma2(a2[r], bv[p], acc[r * NP + p]);
            }
        }
        cp_wait0();
        __syncthreads();
    }
}

// ---------------- main fused recurrent kernel ----------------
__global__ void __launch_bounds__(NTHREADS, 1)
TinyRecurrentWorkshop_69054484185493_kernel(
    const float* __restrict__ x,
    const float* __restrict__ ln_w, const float* __restrict__ ln_b,
    const float* __restrict__ w1, const float* __restrict__ b1,
    const float* __restrict__ w2, const float* __restrict__ b2,
    const float* __restrict__ wg, const float* __restrict__ bg,
    const int* __restrict__ passes_p,
    float* __restrict__ out) {
    extern __shared__ float smem[];
    float* sS = smem;            // state:       128 x 132
    float* sA = smem + SA_OFF;   // h / act / r: 128 x 256
    float* sW = smem + SW_OFF;   // weight tiles: 2 x 4096

    const int tid = threadIdx.x;
    const int tr = tid >> 4;  // 0..15 : rows tr*8 .. tr*8+7
    const int tc = tid & 15;  // 0..15 : col group
    const long long rowBase = (long long)blockIdx.x * TM;

    // ---- load state tile ----
    {
        const float4* xg = (const float4*)(x + rowBase * DIMK);
#pragma unroll
        for (int i = 0; i < (TM * DIMK / 4) / NTHREADS; i++) {
            int idx = tid + i * NTHREADS;
            int row = idx >> 5;
            int c4 = idx & 31;
            *(float4*)&sS[row * SSTRIDE + c4 * 4] = xg[idx];
        }
    }

    // robust read of 'passes' (int32 / int64 / accidental-float all handled)
    int npass = passes_p[0];
    if (npass < 1 || npass > 1024) {
        float f = __int_as_float(npass);
        npass = (int)f;
        if (npass < 1 || npass > 1024) npass = 8;
    }
    __syncthreads();

    const int lrow = tid >> 1;  // 2 threads / row for LN
    const int lhalf = tid & 1;

    for (int pass = 0; pass < npass; pass++) {
        // ---------- LayerNorm: h -> sA[:, 0:128] ----------
        {
            float4 xv[16];
            const float* srow = sS + lrow * SSTRIDE + lhalf * 64;
            float s = 0.f;
#pragma unroll
            for (int j = 0; j < 16; j++) {
                xv[j] = *(const float4*)(srow + j * 4);
                s += (xv[j].x + xv[j].y) + (xv[j].z + xv[j].w);
            }
            s += __shfl_xor_sync(0xFFFFFFFFu, s, 1);
            const float mu = s * (1.0f / 128.0f);
            float q = 0.f;
#pragma unroll
            for (int j = 0; j < 16; j++) {
                float d0 = xv[j].x - mu, d1 = xv[j].y - mu;
                float d2 = xv[j].z - mu, d3 = xv[j].w - mu;
                q += d0 * d0 + d1 * d1 + d2 * d2 + d3 * d3;
            }
            q += __shfl_xor_sync(0xFFFFFFFFu, q, 1);
            const float rstd = rsqrtf(q * (1.0f / 128.0f) + 1e-5f);
            float* hrow = sA + lrow * ASTRIDE + lhalf * 64;
#pragma unroll
            for (int j = 0; j < 16; j++) {
                float4 wv = __ldg((const float4*)ln_w + lhalf * 16 + j);
                float4 bv = __ldg((const float4*)ln_b + lhalf * 16 + j);
                float4 h;
                h.x = (xv[j].x - mu) * rstd * wv.x + bv.x;
                h.y = (xv[j].y - mu) * rstd * wv.y + bv.y;
                h.z = (xv[j].z - mu) * rstd * wv.z + bv.z;
                h.w = (xv[j].w - mu) * rstd * wv.w + bv.w;
                *(float4*)(hrow + j * 4) = h;
            }
        }

        // ---------- M1: g = h @ w1  (128x256), tile 8 rows x 16 cols ----------
        unsigned long long acc1[64];
#pragma unroll
        for (int i = 0; i < 64; i++) acc1[i] = 0ULL;
        gemm_seg<256, 16, 8>(sA, ASTRIDE, w1, sW, acc1, tr, tc);

        // gelu(g + b1) -> sA (full 128x256)
        {
            float b1v[16];
#pragma unroll
            for (int j = 0; j < 4; j++) {
                float4 t4 = __ldg((const float4*)(b1 + tc * 16) + j);
                b1v[4 * j + 0] = t4.x; b1v[4 * j + 1] = t4.y;
                b1v[4 * j + 2] = t4.z; b1v[4 * j + 3] = t4.w;
            }
#pragma unroll
            for (int r = 0; r < 8; r++) {
                float* arow = sA + (tr * 8 + r) * ASTRIDE + tc * 16;
#pragma unroll
                for (int p = 0; p < 8; p += 2) {
                    float2 u0 = unpack2(acc1[r * 8 + p]);
                    float2 u1 = unpack2(acc1[r * 8 + p + 1]);
                    float4 o;
                    o.x = gelu_f(u0.x + b1v[2 * p + 0]);
                    o.y = gelu_f(u0.y + b1v[2 * p + 1]);
                    o.z = gelu_f(u1.x + b1v[2 * p + 2]);
                    o.w = gelu_f(u1.y + b1v[2 * p + 3]);
                    *(float4*)(arow + 2 * p) = o;
                }
            }
        }

        // ---------- M2: refined = a @ w2 + b2  (K=256), tile 8x8 ----------
        unsigned long long acc2[32];
#pragma unroll
        for (int i = 0; i < 32; i++) acc2[i] = 0ULL;
        gemm_seg<128, 32, 4>(sA, ASTRIDE, w2, sW, acc2, tr, tc);
        gemm_seg<128, 32, 4>(sA + 128, ASTRIDE, w2 + 128 * 128, sW, acc2, tr, tc);

        float rf[64];
        {
            float b2v[8];
            {
                float4 t0 = __ldg((const float4*)(b2 + tc * 8) + 0);
                float4 t1 = __ldg((const float4*)(b2 + tc * 8) + 1);
                b2v[0] = t0.x; b2v[1] = t0.y; b2v[2] = t0.z; b2v[3] = t0.w;
                b2v[4] = t1.x; b2v[5] = t1.y; b2v[6] = t1.z; b2v[7] = t1.w;
            }
#pragma unroll
            for (int r = 0; r < 8; r++) {
#pragma unroll
                for (int p = 0; p < 4; p++) {
                    float2 u = unpack2(acc2[r * 4 + p]);
                    rf[r * 8 + 2 * p + 0] = u.x + b2v[2 * p + 0];
                    rf[r * 8 + 2 * p + 1] = u.y + b2v[2 * p + 1];
                }
                // write refined into sA[:, 0:128] (a no longer needed)
                float4 wlo, whi;
                wlo.x = rf[r * 8 + 0]; wlo.y = rf[r * 8 + 1];
                wlo.z = rf[r * 8 + 2]; wlo.w = rf[r * 8 + 3];
                whi.x = rf[r * 8 + 4]; whi.y = rf[r * 8 + 5];
                whi.z = rf[r * 8 + 6]; whi.w = rf[r * 8 + 7];
                float* arow = sA + (tr * 8 + r) * ASTRIDE + tc * 8;
                *(float4*)(arow) = wlo;
                *(float4*)(arow + 4) = whi;
            }
        }

        // ---------- M3: z = state @ wg_s + refined @ wg_r + bg ----------
        unsigned long long acc3[32];
#pragma unroll
        for (int i = 0; i < 32; i++) acc3[i] = 0ULL;
        gemm_seg<128, 32, 4>(sS, SSTRIDE, wg, sW, acc3, tr, tc);           // state half
        gemm_seg<128, 32, 4>(sA, ASTRIDE, wg + 128 * 128, sW, acc3, tr, tc);  // refined half

        // gate + residual update (thread owns exactly its own state elems)
        {
            float bgv[8];
            {
                float4 t0 = __ldg((const float4*)(bg + tc * 8) + 0);
                float4 t1 = __ldg((const float4*)(bg + tc * 8) + 1);
                bgv[0] = t0.x; bgv[1] = t0.y; bgv[2] = t0.z; bgv[3] = t0.w;
                bgv[4] = t1.x; bgv[5] = t1.y; bgv[6] = t1.z; bgv[7] = t1.w;
            }
#pragma unroll
            for (int r = 0; r < 8; r++) {
#pragma unroll
                for (int p = 0; p < 4; p++) {
                    float2 z = unpack2(acc3[r * 4 + p]);
                    float z0 = z.x + bgv[2 * p + 0];
                    float z1 = z.y + bgv[2 * p + 1];
                    float g0 = 1.0f / (1.0f + expf(-z0));
                    float g1 = 1.0f / (1.0f + expf(-z1));
                    int si = (tr * 8 + r) * SSTRIDE + tc * 8 + 2 * p;
                    sS[si + 0] += g0 * rf[r * 8 + 2 * p + 0];
                    sS[si + 1] += g1 * rf[r * 8 + 2 * p + 1];
                }
            }
        }
        __syncthreads();  // state update visible to next pass's LN
    }

    // ---- store result ----
    {
        float4* og = (float4*)(out + rowBase * DIMK);
#pragma unroll
        for (int i = 0; i < (TM * DIMK / 4) / NTHREADS; i++) {
            int idx = tid + i * NTHREADS;
            int row = idx >> 5;
            int c4 = idx & 31;
            og[idx] = *(const float4*)&sS[row * SSTRIDE + c4 * 4];
        }
    }
}

extern "C" void kernel_launch(void* const* d_in, const int* in_sizes, int n_in,
                              void* d_out, int out_size) {
    const float* x    = (const float*)d_in[0];
    const float* ln_w = (const float*)d_in[1];
    const float* ln_b = (const float*)d_in[2];
    const float* w1   = (const float*)d_in[3];
    const float* b1   = (const float*)d_in[4];
    const float* w2   = (const float*)d_in[5];
    const float* b2   = (const float*)d_in[6];
    const float* wg   = (const float*)d_in[7];
    const float* bg   = (const float*)d_in[8];
    const int* passes = (const int*)d_in[9];
    float* out = (float*)d_out;

    const int nrows = in_sizes[0] / DIMK;
    const int blocks = nrows / TM;

    cudaFuncSetAttribute(TinyRecurrentWorkshop_69054484185493_kernel,
                         cudaFuncAttributeMaxDynamicSharedMemorySize, SMEM_BYTES);
    TinyRecurrentWorkshop_69054484185493_kernel<<<blocks, NTHREADS, SMEM_BYTES>>>(
        x, ln_w, ln_b, w1, b1, w2, b2, wg, bg, passes, out);
}

// round 5
// speedup vs baseline: 1.1687x; 1.1687x over previous
#include <cuda_runtime.h>
#include <cstdint>
#include <math.h>

#define DIMK 128
#define TM 128
#define NTHREADS 512
#define SSTRIDE 132
#define ASTRIDE 256

#define SA_OFF (TM * SSTRIDE)              /* 16896 floats */
#define SW_OFF (SA_OFF + TM * ASTRIDE)     /* 49664 floats */
#define SW_TILE 4096
#define SMEM_FLOATS (SW_OFF + 2 * SW_TILE) /* 57856 floats */
#define SMEM_BYTES (SMEM_FLOATS * 4)       /* 231424 bytes */

typedef unsigned long long u64;

// ---------------- packed f32x2 helpers (Blackwell FFMA2) ----------------
__device__ __forceinline__ u64 fma2(u64 a, u64 b, u64 c) {
    u64 d;
    asm("fma.rn.f32x2 %0, %1, %2, %3;" : "=l"(d) : "l"(a), "l"(b), "l"(c));
    return d;
}
__device__ __forceinline__ u64 pack_dup(float a) {
    u64 d;
    asm("mov.b64 %0, {%1, %1};" : "=l"(d) : "f"(a));
    return d;
}
__device__ __forceinline__ float2 unpack2(u64 v) {
    float lo, hi;
    asm("mov.b64 {%0, %1}, %2;" : "=f"(lo), "=f"(hi) : "l"(v));
    return make_float2(lo, hi);
}

// ---------------- cp.async helpers ----------------
__device__ __forceinline__ void cp_async16(unsigned saddr, const void* g) {
    asm volatile("cp.async.ca.shared.global [%0], [%1], 16;" ::"r"(saddr), "l"(g));
}
__device__ __forceinline__ void cp_commit() {
    asm volatile("cp.async.commit_group;" ::: "memory");
}
__device__ __forceinline__ void cp_wait0() {
    asm volatile("cp.async.wait_group 0;" ::: "memory");
}

// prefetch one 4096-float (16 KB) weight tile: 512 threads x 2 float4
__device__ __forceinline__ void prefetch_tile(float* sdst, const float* g) {
    unsigned s = (unsigned)__cvta_generic_to_shared(sdst);
    const float4* g4 = (const float4*)g;
    int tid = threadIdx.x;
    cp_async16(s + (tid)*16, g4 + tid);
    cp_async16(s + (tid + 512) * 16, g4 + tid + 512);
    cp_commit();
}

__device__ __forceinline__ float gelu_f(float x) {
    return 0.5f * x * (1.0f + erff(x * 0.7071067811865476f));
}

// ---------------- M1 GEMM: C[128x256] = Hdup[128x(128dup)] * B[128x256] ----
// A (h) is stored DUPLICATED in sA: sA[row*256 + 2k] = sA[row*256 + 2k+1] = h[row][k]
// -> A loads are already packed f32x2, zero packing MOVs.
// Thread map: warp w (tid>>5) owns rows w*8..w*8+7; lane owns col pairs
// (64p + 2*lane, 64p + 2*lane + 1), p = 0..3.  All lane LDS are conflict-free.
__device__ __forceinline__ void gemm_m1(const float* __restrict__ Arow,
                                        const float* __restrict__ Bg,
                                        float* sW, u64* acc, int lane) {
    prefetch_tile(sW, Bg);
    cp_wait0();
    __syncthreads();
    for (int t = 0; t < 8; t++) {
        if (t + 1 < 8) prefetch_tile(sW + ((t + 1) & 1) * SW_TILE, Bg + (t + 1) * SW_TILE);
        const float* sB = sW + (t & 1) * SW_TILE;
#pragma unroll
        for (int k2 = 0; k2 < 8; k2++) {
            const int k0 = t * 16 + k2 * 2;
            ulonglong2 a[8];
#pragma unroll
            for (int r = 0; r < 8; r++)
                a[r] = *(const ulonglong2*)(Arow + r * ASTRIDE + 2 * k0);
#pragma unroll
            for (int kk = 0; kk < 2; kk++) {
                const u64* bp = (const u64*)(sB + (k2 * 2 + kk) * 256) + lane;
                u64 b0 = bp[0], b1 = bp[32], b2 = bp[64], b3 = bp[96];
#pragma unroll
                for (int r = 0; r < 8; r++) {
                    u64 av = kk ? a[r].y : a[r].x;
                    acc[r * 4 + 0] = fma2(av, b0, acc[r * 4 + 0]);
                    acc[r * 4 + 1] = fma2(av, b1, acc[r * 4 + 1]);
                    acc[r * 4 + 2] = fma2(av, b2, acc[r * 4 + 2]);
                    acc[r * 4 + 3] = fma2(av, b3, acc[r * 4 + 3]);
                }
            }
        }
        cp_wait0();
        __syncthreads();
    }
}

// ---------------- M2/M3 GEMM segment: C[128x128] += A[128x128] * B[128x128] -
// Thread map: warp w rows w*8 + (lane>>4)*4 .. +3 ; h = lane&15 owns col pairs
// (32p + 2h, 32p + 2h + 1), p = 0..3.  Lane-consecutive LDS.64 -> conflict-free.
__device__ __forceinline__ void gemm_sc(const float* __restrict__ Arow, int astride,
                                        const float* __restrict__ Bg,
                                        float* sW, u64* acc, int h) {
    prefetch_tile(sW, Bg);
    cp_wait0();
    __syncthreads();
    for (int t = 0; t < 4; t++) {
        if (t + 1 < 4) prefetch_tile(sW + ((t + 1) & 1) * SW_TILE, Bg + (t + 1) * SW_TILE);
        const float* sB = sW + (t & 1) * SW_TILE;
#pragma unroll
        for (int k4 = 0; k4 < 8; k4++) {
            float4 av[4];
#pragma unroll
            for (int r = 0; r < 4; r++)
                av[r] = *(const float4*)(Arow + r * astride + t * 32 + k4 * 4);
#pragma unroll
            for (int kk = 0; kk < 4; kk++) {
                u64 ad[4];
#pragma unroll
                for (int r = 0; r < 4; r++)
                    ad[r] = pack_dup(((const float*)&av[r])[kk]);
                const u64* bp = (const u64*)(sB + (k4 * 4 + kk) * 128) + h;
                u64 b0 = bp[0], b1 = bp[16], b2 = bp[32], b3 = bp[48];
#pragma unroll
                for (int r = 0; r < 4; r++) {
                    acc[r * 4 + 0] = fma2(ad[r], b0, acc[r * 4 + 0]);
                    acc[r * 4 + 1] = fma2(ad[r], b1, acc[r * 4 + 1]);
                    acc[r * 4 + 2] = fma2(ad[r], b2, acc[r * 4 + 2]);
                    acc[r * 4 + 3] = fma2(ad[r], b3, acc[r * 4 + 3]);
                }
            }
        }
        cp_wait0();
        __syncthreads();
    }
}

// ---------------- main fused recurrent kernel ----------------
__global__ void __launch_bounds__(NTHREADS, 1)
TinyRecurrentWorkshop_69054484185493_kernel(
    const float* __restrict__ x,
    const float* __restrict__ ln_w, const float* __restrict__ ln_b,
    const float* __restrict__ w1, const float* __restrict__ b1,
    const float* __restrict__ w2, const float* __restrict__ b2,
    const float* __restrict__ wg, const float* __restrict__ bg,
    const int* __restrict__ passes_p,
    float* __restrict__ out) {
    extern __shared__ float smem[];
    float* sS = smem;            // state:          128 x 132
    float* sA = smem + SA_OFF;   // hdup / act / r: 128 x 256
    float* sW = smem + SW_OFF;   // weight tiles:   2 x 4096

    const int tid = threadIdx.x;
    const int w = tid >> 5;
    const int lane = tid & 31;
    const int h = lane & 15;
    const int w2r = w * 8 + ((lane >> 4) << 2);  // first row for M2/M3 map
    const long long rowBase = (long long)blockIdx.x * TM;

    // ---- load state tile ----
    {
        const float4* xg = (const float4*)(x + rowBase * DIMK);
#pragma unroll
        for (int i = 0; i < (TM * DIMK / 4) / NTHREADS; i++) {
            int idx = tid + i * NTHREADS;
            *(float4*)&sS[(idx >> 5) * SSTRIDE + (idx & 31) * 4] = xg[idx];
        }
    }

    int npass = passes_p[0];
    if (npass < 1 || npass > 1024) {
        float f = __int_as_float(npass);
        npass = (int)f;
        if (npass < 1 || npass > 1024) npass = 8;
    }
    __syncthreads();

    const int lrow = tid >> 2;  // 4 threads / row for LN
    const int lq = tid & 3;

    for (int pass = 0; pass < npass; pass++) {
        // ---------- LayerNorm -> h DUPLICATED into sA (128 x 256) ----------
        {
            float4 xv[8];
            const float* srow = sS + lrow * SSTRIDE + lq * 32;
            float s = 0.f;
#pragma unroll
            for (int j = 0; j < 8; j++) {
                xv[j] = *(const float4*)(srow + j * 4);
                s += (xv[j].x + xv[j].y) + (xv[j].z + xv[j].w);
            }
            s += __shfl_xor_sync(0xFFFFFFFFu, s, 1);
            s += __shfl_xor_sync(0xFFFFFFFFu, s, 2);
            const float mu = s * (1.0f / 128.0f);
            float q = 0.f;
#pragma unroll
            for (int j = 0; j < 8; j++) {
                float d0 = xv[j].x - mu, d1 = xv[j].y - mu;
                float d2 = xv[j].z - mu, d3 = xv[j].w - mu;
                q += d0 * d0 + d1 * d1 + d2 * d2 + d3 * d3;
            }
            q += __shfl_xor_sync(0xFFFFFFFFu, q, 1);
            q += __shfl_xor_sync(0xFFFFFFFFu, q, 2);
            const float rstd = rsqrtf(q * (1.0f / 128.0f) + 1e-5f);
            float* hrow = sA + lrow * ASTRIDE + lq * 64;
#pragma unroll
            for (int j = 0; j < 8; j++) {
                float4 wv = __ldg((const float4*)ln_w + lq * 8 + j);
                float4 bv = __ldg((const float4*)ln_b + lq * 8 + j);
                float h0 = (xv[j].x - mu) * rstd * wv.x + bv.x;
                float h1 = (xv[j].y - mu) * rstd * wv.y + bv.y;
                float h2 = (xv[j].z - mu) * rstd * wv.z + bv.z;
                float h3 = (xv[j].w - mu) * rstd * wv.w + bv.w;
                float4 d0 = make_float4(h0, h0, h1, h1);
                float4 d1 = make_float4(h2, h2, h3, h3);
                *(float4*)(hrow + j * 8) = d0;
                *(float4*)(hrow + j * 8 + 4) = d1;
            }
        }

        // ---------- M1: g = h @ w1 (128x256) ----------
        u64 acc1[32];
#pragma unroll
        for (int i = 0; i < 32; i++) acc1[i] = 0ULL;
        gemm_m1(sA + (w * 8) * ASTRIDE, w1, sW, acc1, lane);

        // gelu(g + b1) -> sA (overwrites hdup; safe after mainloop sync)
        {
            float2 b1v[4];
#pragma unroll
            for (int p = 0; p < 4; p++)
                b1v[p] = __ldg((const float2*)(b1 + 64 * p + 2 * lane));
#pragma unroll
            for (int r = 0; r < 8; r++) {
                float* arow = sA + (w * 8 + r) * ASTRIDE;
#pragma unroll
                for (int p = 0; p < 4; p++) {
                    float2 u = unpack2(acc1[r * 4 + p]);
                    float2 o;
                    o.x = gelu_f(u.x + b1v[p].x);
                    o.y = gelu_f(u.y + b1v[p].y);
                    *(float2*)(arow + 64 * p + 2 * lane) = o;
                }
            }
        }

        // ---------- M2: refined = gelu_act @ w2 + b2 (K = 256) ----------
        u64 acc2[16];
#pragma unroll
        for (int i = 0; i < 16; i++) acc2[i] = 0ULL;
        gemm_sc(sA + w2r * ASTRIDE, ASTRIDE, w2, sW, acc2, h);
        gemm_sc(sA + w2r * ASTRIDE + 128, ASTRIDE, w2 + 128 * 128, sW, acc2, h);

        float rf[32];
        {
            float2 b2v[4];
#pragma unroll
            for (int p = 0; p < 4; p++)
                b2v[p] = __ldg((const float2*)(b2 + 32 * p + 2 * h));
#pragma unroll
            for (int r = 0; r < 4; r++) {
                float* arow = sA + (w2r + r) * ASTRIDE;
#pragma unroll
                for (int p = 0; p < 4; p++) {
                    float2 u = unpack2(acc2[r * 4 + p]);
                    float v0 = u.x + b2v[p].x;
                    float v1 = u.y + b2v[p].y;
                    rf[r * 8 + 2 * p + 0] = v0;
                    rf[r * 8 + 2 * p + 1] = v1;
                    *(float2*)(arow + 32 * p + 2 * h) = make_float2(v0, v1);
                }
            }
        }

        // ---------- M3: z = state @ wg_s + refined @ wg_r + bg ----------
        u64 acc3[16];
#pragma unroll
        for (int i = 0; i < 16; i++) acc3[i] = 0ULL;
        gemm_sc(sS + w2r * SSTRIDE, SSTRIDE, wg, sW, acc3, h);            // state half
        gemm_sc(sA + w2r * ASTRIDE, ASTRIDE, wg + 128 * 128, sW, acc3, h);  // refined half

        // gate + residual update (thread owns its state elems)
        {
            float2 bgv[4];
#pragma unroll
            for (int p = 0; p < 4; p++)
                bgv[p] = __ldg((const float2*)(bg + 32 * p + 2 * h));
#pragma unroll
            for (int r = 0; r < 4; r++) {
#pragma unroll
                for (int p = 0; p < 4; p++) {
                    float2 z = unpack2(acc3[r * 4 + p]);
                    float z0 = z.x + bgv[p].x;
                    float z1 = z.y + bgv[p].y;
                    float g0 = 1.0f / (1.0f + expf(-z0));
                    float g1 = 1.0f / (1.0f + expf(-z1));
                    int si = (w2r + r) * SSTRIDE + 32 * p + 2 * h;
                    sS[si + 0] += g0 * rf[r * 8 + 2 * p + 0];
                    sS[si + 1] += g1 * rf[r * 8 + 2 * p + 1];
                }
            }
        }
        __syncthreads();  // state update visible to next pass's LN
    }

    // ---- store result ----
    {
        float4* og = (float4*)(out + rowBase * DIMK);
#pragma unroll
        for (int i = 0; i < (TM * DIMK / 4) / NTHREADS; i++) {
            int idx = tid + i * NTHREADS;
            og[idx] = *(const float4*)&sS[(idx >> 5) * SSTRIDE + (idx & 31) * 4];
        }
    }
}

extern "C" void kernel_launch(void* const* d_in, const int* in_sizes, int n_in,
                              void* d_out, int out_size) {
    const float* x    = (const float*)d_in[0];
    const float* ln_w = (const float*)d_in[1];
    const float* ln_b = (const float*)d_in[2];
    const float* w1   = (const float*)d_in[3];
    const float* b1   = (const float*)d_in[4];
    const float* w2   = (const float*)d_in[5];
    const float* b2   = (const float*)d_in[6];
    const float* wg   = (const float*)d_in[7];
    const float* bg   = (const float*)d_in[8];
    const int* passes = (const int*)d_in[9];
    float* out = (float*)d_out;

    const int nrows = in_sizes[0] / DIMK;
    const int blocks = nrows / TM;

    cudaFuncSetAttribute(TinyRecurrentWorkshop_69054484185493_kernel,
                         cudaFuncAttributeMaxDynamicSharedMemorySize, SMEM_BYTES);
    TinyRecurrentWorkshop_69054484185493_kernel<<<blocks, NTHREADS, SMEM_BYTES>>>(
        x, ln_w, ln_b, w1, b1, w2, b2, wg, bg, passes, out);
}